// round 2
// baseline (speedup 1.0000x reference)
#include <cuda_runtime.h>
#include <math.h>

// Problem dims (fixed by the dataset)
namespace {
constexpr int S_  = 256;   // sequence length
constexpr int B_  = 256;   // batch
constexpr int I_  = 256;   // input size
constexpr int H_  = 512;   // hidden size
constexpr int L_  = 2;     // layers
constexpr int G4_ = 4 * H_;      // 2048 gate width
constexpr int BH_ = B_ * H_;     // 131072
}

typedef unsigned long long u64;

// Packed fp32x2 helpers (Blackwell: FFMA2 is 2x the rate of scalar FFMA)
__device__ __forceinline__ u64 pack2(float lo, float hi) {
    u64 r; asm("mov.b64 %0, {%1,%2};" : "=l"(r) : "f"(lo), "f"(hi)); return r;
}
__device__ __forceinline__ u64 fma2(u64 a, u64 b, u64 c) {
    u64 d; asm("fma.rn.f32x2 %0, %1, %2, %3;" : "=l"(d) : "l"(a), "l"(b), "l"(c)); return d;
}
__device__ __forceinline__ float2 unpack2(u64 v) {
    float2 f; asm("mov.b64 {%0,%1}, %2;" : "=f"(f.x), "=f"(f.y) : "l"(v)); return f;
}

// Scratch (device globals: allocation-free rule)
__device__ __align__(16) float g_G[(size_t)S_ * B_ * G4_];    // gate preactivations (reused per layer)
__device__ __align__(16) float g_H0raw[(size_t)S_ * B_ * H_]; // layer-0 unmasked hidden stream
__device__ __align__(16) float g_hbuf[2 * BH_];               // double-buffered h state
__device__ __align__(16) float g_cbuf[BH_];                   // c state (owner-written, in-place safe)

// ---------------------------------------------------------------------------
// SGEMM with fused bias: C[m,n] = sum_k A[m,k] * W[n,k] + bi[n] + bh[n]
// A: M x K row-major, W: N x K row-major. 128x128 tile, BK=8, 256 threads,
// 8x8 per thread via packed f32x2 FMAs, global->reg prefetch of next slab.
// ---------------------------------------------------------------------------
__global__ __launch_bounds__(256) void gemm_bias_kernel(
    const float* __restrict__ A, const float* __restrict__ W,
    const float* __restrict__ bi, const float* __restrict__ bh,
    float* __restrict__ C, int M, int N, int K)
{
    __shared__ __align__(16) float As[8][128];
    __shared__ __align__(16) float Bs[8][128];
    const int tid = threadIdx.x;
    const int m0 = blockIdx.y * 128;
    const int n0 = blockIdx.x * 128;
    const int lr = tid >> 1;          // 0..127
    const int lc = (tid & 1) * 4;     // 0 or 4
    const int tx = tid & 15;
    const int ty = tid >> 4;

    u64 acc2[8][4];
#pragma unroll
    for (int i = 0; i < 8; i++)
#pragma unroll
        for (int j = 0; j < 4; j++) acc2[i][j] = 0ull;

    const float* Ag = A + (size_t)(m0 + lr) * K + lc;
    const float* Wg = W + (size_t)(n0 + lr) * K + lc;

    float4 a4 = *(const float4*)(Ag);
    float4 w4 = *(const float4*)(Wg);

    for (int k0 = 0; k0 < K; k0 += 8) {
        As[lc + 0][lr] = a4.x; As[lc + 1][lr] = a4.y;
        As[lc + 2][lr] = a4.z; As[lc + 3][lr] = a4.w;
        Bs[lc + 0][lr] = w4.x; Bs[lc + 1][lr] = w4.y;
        Bs[lc + 2][lr] = w4.z; Bs[lc + 3][lr] = w4.w;
        __syncthreads();
        if (k0 + 8 < K) {                       // prefetch next slab
            a4 = *(const float4*)(Ag + k0 + 8);
            w4 = *(const float4*)(Wg + k0 + 8);
        }
#pragma unroll
        for (int kk = 0; kk < 8; kk++) {
            // a-fragment: 8 row values, duplicated into f32x2 lanes
            const float* ap = &As[kk][ty * 8];
            // b-fragment: 4 packed pairs straight from smem (16B-aligned rows)
            const u64* bp = (const u64*)&Bs[kk][tx * 8];
            u64 b0 = bp[0], b1 = bp[1], b2 = bp[2], b3 = bp[3];
#pragma unroll
            for (int i = 0; i < 8; i++) {
                u64 aa = pack2(ap[i], ap[i]);
                acc2[i][0] = fma2(aa, b0, acc2[i][0]);
                acc2[i][1] = fma2(aa, b1, acc2[i][1]);
                acc2[i][2] = fma2(aa, b2, acc2[i][2]);
                acc2[i][3] = fma2(aa, b3, acc2[i][3]);
            }
        }
        __syncthreads();
    }

    // bias (hoisted)
    float bias[8];
#pragma unroll
    for (int j = 0; j < 8; j++) {
        int n = n0 + tx * 8 + j;
        bias[j] = bi[n] + bh[n];
    }
#pragma unroll
    for (int i = 0; i < 8; i++) {
        size_t row = (size_t)(m0 + ty * 8 + i) * N + n0 + tx * 8;
        float2 p0 = unpack2(acc2[i][0]);
        float2 p1 = unpack2(acc2[i][1]);
        float2 p2 = unpack2(acc2[i][2]);
        float2 p3 = unpack2(acc2[i][3]);
        float4 v0 = {p0.x + bias[0], p0.y + bias[1], p1.x + bias[2], p1.y + bias[3]};
        float4 v1 = {p2.x + bias[4], p2.y + bias[5], p3.x + bias[6], p3.y + bias[7]};
        *(float4*)(C + row)     = v0;
        *(float4*)(C + row + 4) = v1;
    }
}

// ---------------------------------------------------------------------------
// Fused recurrent step: gates = G[t] + h_in @ Whh^T, then LSTM cell + mask.
// Each CTA computes a 32(batch) x 32(hidden) tile of ALL FOUR gates so the
// cell update fuses into the epilogue. h double-buffered, c in-place.
// Grid: (H/32, B/32), 256 threads. Thread = 1 batch row x 4 hidden cols.
// ---------------------------------------------------------------------------
__global__ __launch_bounds__(256) void lstm_step_kernel(
    const float* __restrict__ G,      // S*B x 4H (includes both biases)
    const float* __restrict__ h_in,   // B x H
    float* __restrict__ h_out,        // B x H (masked)
    float* __restrict__ c_st,         // B x H (in/out, masked)
    const float* __restrict__ done,   // S x B
    const float* __restrict__ Whh,    // 4H x H
    float* __restrict__ raw_out,      // S x B x H (unmasked h_new stream)
    int t)
{
    __shared__ __align__(16) float Hs[32][33];      // padded: conflict-free
    __shared__ __align__(16) float Ws[4][32][36];   // [gate][kk][n], row pad 36 (16B-aligned rows)

    const int tid = threadIdx.x;
    const int nt0 = blockIdx.x * 32;
    const int bt0 = blockIdx.y * 32;
    const int tx = tid & 7;    // 0..7  -> 4 hidden cols each
    const int ty = tid >> 3;   // 0..31 -> batch row

    u64 acc2[4][2];
#pragma unroll
    for (int g = 0; g < 4; g++) { acc2[g][0] = 0ull; acc2[g][1] = 0ull; }

    const float* hrow = h_in + (size_t)(bt0 + ty) * H_ + tx * 4;

    for (int k0 = 0; k0 < H_; k0 += 32) {
        // load h tile (32 batch x 32 k)
        float4 h4 = *(const float4*)(hrow + k0);
        Hs[ty][tx * 4 + 0] = h4.x; Hs[ty][tx * 4 + 1] = h4.y;
        Hs[ty][tx * 4 + 2] = h4.z; Hs[ty][tx * 4 + 3] = h4.w;
        // load 4 gate weight tiles, transposed to [kk][n]
#pragma unroll
        for (int g = 0; g < 4; g++) {
            float4 w4 = *(const float4*)(Whh + (size_t)(g * H_ + nt0 + ty) * H_ + k0 + tx * 4);
            Ws[g][tx * 4 + 0][ty] = w4.x; Ws[g][tx * 4 + 1][ty] = w4.y;
            Ws[g][tx * 4 + 2][ty] = w4.z; Ws[g][tx * 4 + 3][ty] = w4.w;
        }
        __syncthreads();
#pragma unroll
        for (int kk = 0; kk < 32; kk++) {
            u64 aa = pack2(Hs[ty][kk], Hs[ty][kk]);
#pragma unroll
            for (int g = 0; g < 4; g++) {
                const u64* wp = (const u64*)&Ws[g][kk][tx * 4];  // 16B-aligned
                acc2[g][0] = fma2(aa, wp[0], acc2[g][0]);
                acc2[g][1] = fma2(aa, wp[1], acc2[g][1]);
            }
        }
        __syncthreads();
    }

    // ---- epilogue: add precomputed input gates + cell update + mask ----
    const int b = bt0 + ty;
    const int n = nt0 + tx * 4;
    const float m = 1.0f - done[t * B_ + b];
    const float* Gt = G + (size_t)(t * B_ + b) * G4_;

    float4 gI = *(const float4*)(Gt + 0 * H_ + n);
    float4 gF = *(const float4*)(Gt + 1 * H_ + n);
    float4 gGv = *(const float4*)(Gt + 2 * H_ + n);
    float4 gO = *(const float4*)(Gt + 3 * H_ + n);
    float4 cp = *(const float4*)(c_st + (size_t)b * H_ + n);

    float2 ai0 = unpack2(acc2[0][0]), ai1 = unpack2(acc2[0][1]);
    float2 af0 = unpack2(acc2[1][0]), af1 = unpack2(acc2[1][1]);
    float2 ag0 = unpack2(acc2[2][0]), ag1 = unpack2(acc2[2][1]);
    float2 ao0 = unpack2(acc2[3][0]), ao1 = unpack2(acc2[3][1]);

    float vi[4] = {ai0.x + gI.x,  ai0.y + gI.y,  ai1.x + gI.z,  ai1.y + gI.w};
    float vf[4] = {af0.x + gF.x,  af0.y + gF.y,  af1.x + gF.z,  af1.y + gF.w};
    float vg[4] = {ag0.x + gGv.x, ag0.y + gGv.y, ag1.x + gGv.z, ag1.y + gGv.w};
    float vo[4] = {ao0.x + gO.x,  ao0.y + gO.y,  ao1.x + gO.z,  ao1.y + gO.w};
    float vc[4] = {cp.x, cp.y, cp.z, cp.w};

    float hn[4], cn[4];
#pragma unroll
    for (int c2 = 0; c2 < 4; c2++) {
        float si = 1.0f / (1.0f + __expf(-vi[c2]));
        float sf = 1.0f / (1.0f + __expf(-vf[c2]));
        float so = 1.0f / (1.0f + __expf(-vo[c2]));
        float cnew = sf * vc[c2] + si * tanhf(vg[c2]);
        float hnew = so * tanhf(cnew);
        hn[c2] = hnew;
        cn[c2] = cnew;
    }

    float4 rawv = {hn[0], hn[1], hn[2], hn[3]};
    *(float4*)(raw_out + (size_t)t * BH_ + (size_t)b * H_ + n) = rawv;
    float4 hv = {hn[0] * m, hn[1] * m, hn[2] * m, hn[3] * m};
    *(float4*)(h_out + (size_t)b * H_ + n) = hv;
    float4 cv = {cn[0] * m, cn[1] * m, cn[2] * m, cn[3] * m};
    *(float4*)(c_st + (size_t)b * H_ + n) = cv;
}

// ---------------------------------------------------------------------------
// Small helper: copies two arrays (state init / final-state writeback).
// ---------------------------------------------------------------------------
__global__ void copy2_kernel(const float* __restrict__ a, const float* __restrict__ b,
                             float* __restrict__ oa, float* __restrict__ ob, int n)
{
    int i = blockIdx.x * blockDim.x + threadIdx.x;
    if (i < n) { oa[i] = a[i]; ob[i] = b[i]; }
}

// ---------------------------------------------------------------------------
extern "C" void kernel_launch(void* const* d_in, const int* in_sizes, int n_in,
                              void* d_out, int out_size)
{
    const float* x    = (const float*)d_in[0];
    const float* h0   = (const float*)d_in[1];
    const float* c0   = (const float*)d_in[2];
    const float* done = (const float*)d_in[3];
    const float* Wih0 = (const float*)d_in[4];
    const float* Whh0 = (const float*)d_in[5];
    const float* bih0 = (const float*)d_in[6];
    const float* bhh0 = (const float*)d_in[7];
    const float* Wih1 = (const float*)d_in[8];
    const float* Whh1 = (const float*)d_in[9];
    const float* bih1 = (const float*)d_in[10];
    const float* bhh1 = (const float*)d_in[11];
    float* out = (float*)d_out;

    float *G, *H0raw, *hb, *cb;
    cudaGetSymbolAddress((void**)&G, g_G);
    cudaGetSymbolAddress((void**)&H0raw, g_H0raw);
    cudaGetSymbolAddress((void**)&hb, g_hbuf);
    cudaGetSymbolAddress((void**)&cb, g_cbuf);

    const bool write_states =
        out_size >= (int)((size_t)S_ * BH_ + 2 * (size_t)L_ * BH_);
    float* out_h = out + (size_t)S_ * BH_;              // [L, B, H]
    float* out_c = out + (size_t)S_ * BH_ + (size_t)L_ * BH_;

    const dim3 ggrid(G4_ / 128, (S_ * B_) / 128);       // (16, 512)
    const dim3 sgrid(H_ / 32, B_ / 32);                 // (16, 8)
    const int cblk = (BH_ + 255) / 256;

    // ===================== Layer 0 =====================
    copy2_kernel<<<cblk, 256>>>(h0, c0, hb, cb, BH_);
    // G = x @ Wih0^T + bih0 + bhh0   (M=65536, N=2048, K=256)
    gemm_bias_kernel<<<ggrid, 256>>>(x, Wih0, bih0, bhh0, G, S_ * B_, G4_, I_);
    for (int t = 0; t < S_; t++) {
        lstm_step_kernel<<<sgrid, 256>>>(G, hb + (t & 1) * BH_, hb + ((t + 1) & 1) * BH_,
                                         cb, done, Whh0, H0raw, t);
    }
    // final layer-0 states live in hb[0] (t=255 wrote buffer (255+1)&1 = 0) and cb
    if (write_states)
        copy2_kernel<<<cblk, 256>>>(hb, cb, out_h, out_c, BH_);

    // ===================== Layer 1 =====================
    copy2_kernel<<<cblk, 256>>>(h0 + BH_, c0 + BH_, hb, cb, BH_);
    // G = H0raw @ Wih1^T + bih1 + bhh1   (M=65536, N=2048, K=512)
    gemm_bias_kernel<<<ggrid, 256>>>(H0raw, Wih1, bih1, bhh1, G, S_ * B_, G4_, H_);
    for (int t = 0; t < S_; t++) {
        lstm_step_kernel<<<sgrid, 256>>>(G, hb + (t & 1) * BH_, hb + ((t + 1) & 1) * BH_,
                                         cb, done, Whh1, out /* outputs section */, t);
    }
    if (write_states)
        copy2_kernel<<<cblk, 256>>>(hb, cb, out_h + BH_, out_c + BH_, BH_);
}

// round 3
// speedup vs baseline: 1.5173x; 1.5173x over previous
#include <cuda_runtime.h>
#include <math.h>

// Problem dims (fixed by the dataset)
namespace {
constexpr int S_  = 256;   // sequence length
constexpr int B_  = 256;   // batch
constexpr int I_  = 256;   // input size
constexpr int H_  = 512;   // hidden size
constexpr int L_  = 2;     // layers
constexpr int G4_ = 4 * H_;      // 2048 gate width
constexpr int BH_ = B_ * H_;     // 131072
constexpr int NCTA_ = 128;       // persistent grid (all co-resident, <148 SMs)
constexpr int KC_ = 32;          // h staging chunk (k)
constexpr int HS_STRIDE_ = B_ * (KC_ + 1);          // 256*33 floats per buffer
constexpr int SMEM_BYTES_ = (H_ * 16 + 2 * HS_STRIDE_) * 4;  // 32KB Ws + 2 Hs bufs
}

typedef unsigned long long u64;

// Packed fp32x2 helpers (Blackwell FFMA2: 2x scalar FFMA throughput)
__device__ __forceinline__ u64 pack2(float lo, float hi) {
    u64 r; asm("mov.b64 %0, {%1,%2};" : "=l"(r) : "f"(lo), "f"(hi)); return r;
}
__device__ __forceinline__ u64 fma2(u64 a, u64 b, u64 c) {
    u64 d; asm("fma.rn.f32x2 %0, %1, %2, %3;" : "=l"(d) : "l"(a), "l"(b), "l"(c)); return d;
}
__device__ __forceinline__ float2 unpack2(u64 v) {
    float2 f; asm("mov.b64 {%0,%1}, %2;" : "=f"(f.x), "=f"(f.y) : "l"(v)); return f;
}
__device__ __forceinline__ float fsig(float x) { return 1.0f / (1.0f + __expf(-x)); }
__device__ __forceinline__ float ftanh(float x) {
    float e = __expf(2.0f * x);
    return 1.0f - __fdividef(2.0f, e + 1.0f);
}

// Scratch (device globals: allocation-free rule)
__device__ __align__(16) float g_G[(size_t)S_ * B_ * G4_];    // gate preactivations (reused per layer)
__device__ __align__(16) float g_H0raw[(size_t)S_ * B_ * H_]; // layer-0 unmasked hidden stream
__device__ __align__(16) float g_hbuf[2 * BH_];               // double-buffered h state
__device__ __align__(16) float g_cbuf[BH_];                   // c state (owner-written)
__device__ unsigned g_sync;                                    // grid barrier counter

__global__ void reset_sync_kernel() { g_sync = 0u; }

// ---------------------------------------------------------------------------
// SGEMM with fused bias: C[m,n] = sum_k A[m,k] * W[n,k] + bi[n] + bh[n]
// ---------------------------------------------------------------------------
__global__ __launch_bounds__(256) void gemm_bias_kernel(
    const float* __restrict__ A, const float* __restrict__ W,
    const float* __restrict__ bi, const float* __restrict__ bh,
    float* __restrict__ C, int M, int N, int K)
{
    __shared__ __align__(16) float As[8][128];
    __shared__ __align__(16) float Bs[8][128];
    const int tid = threadIdx.x;
    const int m0 = blockIdx.y * 128;
    const int n0 = blockIdx.x * 128;
    const int lr = tid >> 1;
    const int lc = (tid & 1) * 4;
    const int tx = tid & 15;
    const int ty = tid >> 4;

    u64 acc2[8][4];
#pragma unroll
    for (int i = 0; i < 8; i++)
#pragma unroll
        for (int j = 0; j < 4; j++) acc2[i][j] = 0ull;

    const float* Ag = A + (size_t)(m0 + lr) * K + lc;
    const float* Wg = W + (size_t)(n0 + lr) * K + lc;

    float4 a4 = *(const float4*)(Ag);
    float4 w4 = *(const float4*)(Wg);

    for (int k0 = 0; k0 < K; k0 += 8) {
        As[lc + 0][lr] = a4.x; As[lc + 1][lr] = a4.y;
        As[lc + 2][lr] = a4.z; As[lc + 3][lr] = a4.w;
        Bs[lc + 0][lr] = w4.x; Bs[lc + 1][lr] = w4.y;
        Bs[lc + 2][lr] = w4.z; Bs[lc + 3][lr] = w4.w;
        __syncthreads();
        if (k0 + 8 < K) {
            a4 = *(const float4*)(Ag + k0 + 8);
            w4 = *(const float4*)(Wg + k0 + 8);
        }
#pragma unroll
        for (int kk = 0; kk < 8; kk++) {
            const float* ap = &As[kk][ty * 8];
            const u64* bp = (const u64*)&Bs[kk][tx * 8];
            u64 b0 = bp[0], b1 = bp[1], b2 = bp[2], b3 = bp[3];
#pragma unroll
            for (int i = 0; i < 8; i++) {
                u64 aa = pack2(ap[i], ap[i]);
                acc2[i][0] = fma2(aa, b0, acc2[i][0]);
                acc2[i][1] = fma2(aa, b1, acc2[i][1]);
                acc2[i][2] = fma2(aa, b2, acc2[i][2]);
                acc2[i][3] = fma2(aa, b3, acc2[i][3]);
            }
        }
        __syncthreads();
    }

    float bias[8];
#pragma unroll
    for (int j = 0; j < 8; j++) {
        int n = n0 + tx * 8 + j;
        bias[j] = bi[n] + bh[n];
    }
#pragma unroll
    for (int i = 0; i < 8; i++) {
        size_t row = (size_t)(m0 + ty * 8 + i) * N + n0 + tx * 8;
        float2 p0 = unpack2(acc2[i][0]);
        float2 p1 = unpack2(acc2[i][1]);
        float2 p2 = unpack2(acc2[i][2]);
        float2 p3 = unpack2(acc2[i][3]);
        float4 v0 = {p0.x + bias[0], p0.y + bias[1], p1.x + bias[2], p1.y + bias[3]};
        float4 v1 = {p2.x + bias[4], p2.y + bias[5], p3.x + bias[6], p3.y + bias[7]};
        *(float4*)(C + row)     = v0;
        *(float4*)(C + row + 4) = v1;
    }
}

// ---------------------------------------------------------------------------
// Persistent recurrent kernel: ONE launch runs all 256 steps of one layer.
// Grid = 128 CTAs, all co-resident; device grid barrier between steps.
// CTA owns 4 hidden cols (x4 gates = 16 outputs/batch); its 32KB weight slice
// lives in smem for the whole kernel. Thread = 1 batch row, 16 outputs via
// packed f32x2 FMAs with broadcast LDS.128 weight reads.
// h staged via coalesced __ldcg into double-buffered padded smem chunks.
// ---------------------------------------------------------------------------
__global__ __launch_bounds__(256, 1) void lstm_persist_kernel(
    const float* __restrict__ G,      // S*B x 4H (biases included)
    float* __restrict__ hb,           // 2*B*H double buffer (init in buf 0)
    float* __restrict__ c_st,         // B*H
    const float* __restrict__ done,   // S*B
    const float* __restrict__ Whh,    // 4H x H
    float* __restrict__ raw_out)      // S*B*H unmasked h stream
{
    extern __shared__ float sm[];
    float* Ws = sm;                       // [512][16]  (k-major, 64B rows)
    float* Hs = sm + H_ * 16;             // 2 x [256][33]

    const int tid = threadIdx.x;
    const int nt0 = blockIdx.x * 4;

    // ---- load weight slice once: Ws[k][g*4+c] = Whh[g*H + nt0+c][k] ----
    {
        const int p = tid & 15, g = p >> 2, c = p & 3;
        const float* wrow = Whh + (size_t)(g * H_ + nt0 + c) * H_;
        const int kq = tid >> 4;          // 0..15
#pragma unroll
        for (int it = 0; it < 8; it++) {
            int k4 = (kq + it * 16) * 4;
            float4 v = *(const float4*)(wrow + k4);
            Ws[(k4 + 0) * 16 + p] = v.x;
            Ws[(k4 + 1) * 16 + p] = v.y;
            Ws[(k4 + 2) * 16 + p] = v.z;
            Ws[(k4 + 3) * 16 + p] = v.w;
        }
    }
    __syncthreads();

    const int j8   = tid & 7;             // staging: k-quad within chunk
    const int brow = tid >> 3;            // staging: batch row base

    for (int t = 0; t < S_; t++) {
        const float* h_in = hb + (t & 1) * BH_;
        float* h_out      = hb + ((t + 1) & 1) * BH_;

        u64 acc[8];
#pragma unroll
        for (int p = 0; p < 8; p++) acc[p] = 0ull;

        // prologue: fetch + stage chunk 0
        float4 rb[8];
#pragma unroll
        for (int it = 0; it < 8; it++)
            rb[it] = __ldcg((const float4*)(h_in + (size_t)(it * 32 + brow) * H_ + j8 * 4));
        int buf = 0;
        {
            float* hd = Hs;
#pragma unroll
            for (int it = 0; it < 8; it++) {
                float* d = hd + (it * 32 + brow) * (KC_ + 1) + j8 * 4;
                d[0] = rb[it].x; d[1] = rb[it].y; d[2] = rb[it].z; d[3] = rb[it].w;
            }
        }
        __syncthreads();

        for (int kc = 0; kc < H_; kc += KC_) {
            const bool more = (kc + KC_ < H_);
            if (more) {
#pragma unroll
                for (int it = 0; it < 8; it++)
                    rb[it] = __ldcg((const float4*)(h_in + (size_t)(it * 32 + brow) * H_ + kc + KC_ + j8 * 4));
            }
            // compute on current buffer
            const float* hrow = Hs + buf * HS_STRIDE_ + tid * (KC_ + 1);
            const float* wsk = Ws + kc * 16;
#pragma unroll
            for (int kk = 0; kk < KC_; kk++) {
                float hv = hrow[kk];
                u64 aa = pack2(hv, hv);
                const ulonglong2* wp = (const ulonglong2*)(wsk + kk * 16);
                ulonglong2 w0 = wp[0], w1 = wp[1], w2 = wp[2], w3 = wp[3];
                acc[0] = fma2(aa, w0.x, acc[0]);
                acc[1] = fma2(aa, w0.y, acc[1]);
                acc[2] = fma2(aa, w1.x, acc[2]);
                acc[3] = fma2(aa, w1.y, acc[3]);
                acc[4] = fma2(aa, w2.x, acc[4]);
                acc[5] = fma2(aa, w2.y, acc[5]);
                acc[6] = fma2(aa, w3.x, acc[6]);
                acc[7] = fma2(aa, w3.y, acc[7]);
            }
            __syncthreads();
            if (more) {
                float* hd = Hs + (buf ^ 1) * HS_STRIDE_;
#pragma unroll
                for (int it = 0; it < 8; it++) {
                    float* d = hd + (it * 32 + brow) * (KC_ + 1) + j8 * 4;
                    d[0] = rb[it].x; d[1] = rb[it].y; d[2] = rb[it].z; d[3] = rb[it].w;
                }
                __syncthreads();
                buf ^= 1;
            }
        }

        // ---- epilogue: cell update for batch b = tid, cols nt0..nt0+3 ----
        {
            const int b = tid;
            const float m = 1.0f - done[t * B_ + b];
            const float* Gt = G + ((size_t)t * B_ + b) * G4_ + nt0;
            float4 gI = __ldg((const float4*)(Gt));
            float4 gF = __ldg((const float4*)(Gt + H_));
            float4 gGv = __ldg((const float4*)(Gt + 2 * H_));
            float4 gO = __ldg((const float4*)(Gt + 3 * H_));
            float4 cp = __ldcg((const float4*)(c_st + (size_t)b * H_ + nt0));

            float2 a0 = unpack2(acc[0]), a1 = unpack2(acc[1]);
            float2 a2 = unpack2(acc[2]), a3 = unpack2(acc[3]);
            float2 a4 = unpack2(acc[4]), a5 = unpack2(acc[5]);
            float2 a6 = unpack2(acc[6]), a7 = unpack2(acc[7]);

            float vi[4] = {a0.x + gI.x,  a0.y + gI.y,  a1.x + gI.z,  a1.y + gI.w};
            float vf[4] = {a2.x + gF.x,  a2.y + gF.y,  a3.x + gF.z,  a3.y + gF.w};
            float vg[4] = {a4.x + gGv.x, a4.y + gGv.y, a5.x + gGv.z, a5.y + gGv.w};
            float vo[4] = {a6.x + gO.x,  a6.y + gO.y,  a7.x + gO.z,  a7.y + gO.w};
            float vc[4] = {cp.x, cp.y, cp.z, cp.w};

            float hn[4], cn[4];
#pragma unroll
            for (int c2 = 0; c2 < 4; c2++) {
                float si = fsig(vi[c2]);
                float sf = fsig(vf[c2]);
                float so = fsig(vo[c2]);
                float cnew = sf * vc[c2] + si * ftanh(vg[c2]);
                hn[c2] = so * ftanh(cnew);
                cn[c2] = cnew;
            }

            float4 rawv = {hn[0], hn[1], hn[2], hn[3]};
            *(float4*)(raw_out + (size_t)t * BH_ + (size_t)b * H_ + nt0) = rawv;
            float4 hv4 = {hn[0] * m, hn[1] * m, hn[2] * m, hn[3] * m};
            *(float4*)(h_out + (size_t)b * H_ + nt0) = hv4;
            float4 cv4 = {cn[0] * m, cn[1] * m, cn[2] * m, cn[3] * m};
            *(float4*)(c_st + (size_t)b * H_ + nt0) = cv4;
        }

        // ---- grid barrier (release: fence+arrive; acquire: spin) ----
        if (t + 1 < S_) {
            __threadfence();
            __syncthreads();
            if (tid == 0) {
                atomicAdd(&g_sync, 1u);
                unsigned target = (unsigned)NCTA_ * (unsigned)(t + 1);
                while (*((volatile unsigned*)&g_sync) < target) { }
            }
            __syncthreads();
        }
    }
}

// ---------------------------------------------------------------------------
__global__ void copy2_kernel(const float* __restrict__ a, const float* __restrict__ b,
                             float* __restrict__ oa, float* __restrict__ ob, int n)
{
    int i = blockIdx.x * blockDim.x + threadIdx.x;
    if (i < n) { oa[i] = a[i]; ob[i] = b[i]; }
}

// ---------------------------------------------------------------------------
extern "C" void kernel_launch(void* const* d_in, const int* in_sizes, int n_in,
                              void* d_out, int out_size)
{
    const float* x    = (const float*)d_in[0];
    const float* h0   = (const float*)d_in[1];
    const float* c0   = (const float*)d_in[2];
    const float* done = (const float*)d_in[3];
    const float* Wih0 = (const float*)d_in[4];
    const float* Whh0 = (const float*)d_in[5];
    const float* bih0 = (const float*)d_in[6];
    const float* bhh0 = (const float*)d_in[7];
    const float* Wih1 = (const float*)d_in[8];
    const float* Whh1 = (const float*)d_in[9];
    const float* bih1 = (const float*)d_in[10];
    const float* bhh1 = (const float*)d_in[11];
    float* out = (float*)d_out;

    float *G, *H0raw, *hb, *cb;
    cudaGetSymbolAddress((void**)&G, g_G);
    cudaGetSymbolAddress((void**)&H0raw, g_H0raw);
    cudaGetSymbolAddress((void**)&hb, g_hbuf);
    cudaGetSymbolAddress((void**)&cb, g_cbuf);

    static bool attr_set = false;
    if (!attr_set) {
        cudaFuncSetAttribute(lstm_persist_kernel,
                             cudaFuncAttributeMaxDynamicSharedMemorySize, SMEM_BYTES_);
        attr_set = true;
    }

    const bool write_states =
        out_size >= (int)((size_t)S_ * BH_ + 2 * (size_t)L_ * BH_);
    float* out_h = out + (size_t)S_ * BH_;
    float* out_c = out + (size_t)S_ * BH_ + (size_t)L_ * BH_;

    const dim3 ggrid(G4_ / 128, (S_ * B_) / 128);
    const int cblk = (BH_ + 255) / 256;

    // ===================== Layer 0 =====================
    copy2_kernel<<<cblk, 256>>>(h0, c0, hb, cb, BH_);
    gemm_bias_kernel<<<ggrid, 256>>>(x, Wih0, bih0, bhh0, G, S_ * B_, G4_, I_);
    reset_sync_kernel<<<1, 1>>>();
    lstm_persist_kernel<<<NCTA_, 256, SMEM_BYTES_>>>(G, hb, cb, done, Whh0, H0raw);
    // final layer-0 h lives in hb[(S_)&1 == 0]
    if (write_states)
        copy2_kernel<<<cblk, 256>>>(hb, cb, out_h, out_c, BH_);

    // ===================== Layer 1 =====================
    copy2_kernel<<<cblk, 256>>>(h0 + BH_, c0 + BH_, hb, cb, BH_);
    gemm_bias_kernel<<<ggrid, 256>>>(H0raw, Wih1, bih1, bhh1, G, S_ * B_, G4_, H_);
    reset_sync_kernel<<<1, 1>>>();
    lstm_persist_kernel<<<NCTA_, 256, SMEM_BYTES_>>>(G, hb, cb, done, Whh1, out);
    if (write_states)
        copy2_kernel<<<cblk, 256>>>(hb, cb, out_h + BH_, out_c + BH_, BH_);
}

// round 5
// speedup vs baseline: 1.6705x; 1.1010x over previous
#include <cuda_runtime.h>
#include <math.h>

// Problem dims (fixed by the dataset)
namespace {
constexpr int S_  = 256;   // sequence length
constexpr int B_  = 256;   // batch
constexpr int I_  = 256;   // input size
constexpr int H_  = 512;   // hidden size
constexpr int L_  = 2;     // layers
constexpr int G4_ = 4 * H_;      // 2048 gate width
constexpr int BH_ = B_ * H_;     // 131072
constexpr int NCTA_ = 128;       // persistent grid (all co-resident, <148 SMs)
constexpr int KC_ = 32;          // h staging chunk (k) per group
constexpr int HSTR_ = 36;        // padded row stride (floats, 144B: 16B-aligned, conflict-free)
constexpr int HBUF_ = B_ * HSTR_;            // 9216 floats per buffer
// smem: Ws 8192 + 4 h-buffers (2 groups x double) + exchange 4096 floats
constexpr int SMEM_FLOATS_ = 8192 + 4 * HBUF_ + 4096;
constexpr int SMEM_BYTES_ = SMEM_FLOATS_ * 4;   // 196608 B
}

typedef unsigned long long u64;

// Packed fp32x2 helpers (Blackwell FFMA2: 2x scalar FFMA throughput)
__device__ __forceinline__ u64 pack2(float lo, float hi) {
    u64 r; asm("mov.b64 %0, {%1,%2};" : "=l"(r) : "f"(lo), "f"(hi)); return r;
}
__device__ __forceinline__ u64 fma2(u64 a, u64 b, u64 c) {
    u64 d; asm("fma.rn.f32x2 %0, %1, %2, %3;" : "=l"(d) : "l"(a), "l"(b), "l"(c)); return d;
}
__device__ __forceinline__ u64 add2(u64 a, u64 b) {
    u64 d; asm("add.rn.f32x2 %0, %1, %2;" : "=l"(d) : "l"(a), "l"(b)); return d;
}
__device__ __forceinline__ float2 unpack2(u64 v) {
    float2 f; asm("mov.b64 {%0,%1}, %2;" : "=f"(f.x), "=f"(f.y) : "l"(v)); return f;
}
__device__ __forceinline__ float fsig(float x) { return 1.0f / (1.0f + __expf(-x)); }
__device__ __forceinline__ float ftanh(float x) {
    float e = __expf(2.0f * x);
    return 1.0f - __fdividef(2.0f, e + 1.0f);
}

// Scratch (device globals: allocation-free rule)
__device__ __align__(16) float g_G[(size_t)S_ * B_ * G4_];    // gate preactivations (reused per layer)
__device__ __align__(16) float g_H0raw[(size_t)S_ * B_ * H_]; // layer-0 unmasked hidden stream
__device__ __align__(16) float g_hbuf[2 * BH_];               // double-buffered h state
__device__ __align__(16) float g_cbuf[BH_];                   // c state (owner-written)
__device__ unsigned g_sync;                                    // grid barrier counter

__global__ void reset_sync_kernel() { g_sync = 0u; }

// ---------------------------------------------------------------------------
// SGEMM with fused bias: C[m,n] = sum_k A[m,k] * W[n,k] + bi[n] + bh[n]
// ---------------------------------------------------------------------------
__global__ __launch_bounds__(256) void gemm_bias_kernel(
    const float* __restrict__ A, const float* __restrict__ W,
    const float* __restrict__ bi, const float* __restrict__ bh,
    float* __restrict__ C, int M, int N, int K)
{
    __shared__ __align__(16) float As[8][128];
    __shared__ __align__(16) float Bs[8][128];
    const int tid = threadIdx.x;
    const int m0 = blockIdx.y * 128;
    const int n0 = blockIdx.x * 128;
    const int lr = tid >> 1;
    const int lc = (tid & 1) * 4;
    const int tx = tid & 15;
    const int ty = tid >> 4;

    u64 acc2[8][4];
#pragma unroll
    for (int i = 0; i < 8; i++)
#pragma unroll
        for (int j = 0; j < 4; j++) acc2[i][j] = 0ull;

    const float* Ag = A + (size_t)(m0 + lr) * K + lc;
    const float* Wg = W + (size_t)(n0 + lr) * K + lc;

    float4 a4 = *(const float4*)(Ag);
    float4 w4 = *(const float4*)(Wg);

    for (int k0 = 0; k0 < K; k0 += 8) {
        As[lc + 0][lr] = a4.x; As[lc + 1][lr] = a4.y;
        As[lc + 2][lr] = a4.z; As[lc + 3][lr] = a4.w;
        Bs[lc + 0][lr] = w4.x; Bs[lc + 1][lr] = w4.y;
        Bs[lc + 2][lr] = w4.z; Bs[lc + 3][lr] = w4.w;
        __syncthreads();
        if (k0 + 8 < K) {
            a4 = *(const float4*)(Ag + k0 + 8);
            w4 = *(const float4*)(Wg + k0 + 8);
        }
#pragma unroll
        for (int kk = 0; kk < 8; kk++) {
            const float* ap = &As[kk][ty * 8];
            const u64* bp = (const u64*)&Bs[kk][tx * 8];
            u64 b0 = bp[0], b1 = bp[1], b2 = bp[2], b3 = bp[3];
#pragma unroll
            for (int i = 0; i < 8; i++) {
                u64 aa = pack2(ap[i], ap[i]);
                acc2[i][0] = fma2(aa, b0, acc2[i][0]);
                acc2[i][1] = fma2(aa, b1, acc2[i][1]);
                acc2[i][2] = fma2(aa, b2, acc2[i][2]);
                acc2[i][3] = fma2(aa, b3, acc2[i][3]);
            }
        }
        __syncthreads();
    }

    float bias[8];
#pragma unroll
    for (int j = 0; j < 8; j++) {
        int n = n0 + tx * 8 + j;
        bias[j] = bi[n] + bh[n];
    }
#pragma unroll
    for (int i = 0; i < 8; i++) {
        size_t row = (size_t)(m0 + ty * 8 + i) * N + n0 + tx * 8;
        float2 p0 = unpack2(acc2[i][0]);
        float2 p1 = unpack2(acc2[i][1]);
        float2 p2 = unpack2(acc2[i][2]);
        float2 p3 = unpack2(acc2[i][3]);
        float4 v0 = {p0.x + bias[0], p0.y + bias[1], p1.x + bias[2], p1.y + bias[3]};
        float4 v1 = {p2.x + bias[4], p2.y + bias[5], p3.x + bias[6], p3.y + bias[7]};
        *(float4*)(C + row)     = v0;
        *(float4*)(C + row + 4) = v1;
    }
}

// ---------------------------------------------------------------------------
// Persistent recurrent kernel: ONE launch runs all 256 steps of one layer.
// Grid = 128 CTAs (co-resident), device grid barrier between steps.
// CTA owns 4 hidden cols (x4 gates). k-split: warps 0-3 take k[0,256),
// warps 4-7 take k[256,512). Thread computes 2 batch rows x 16 outputs via
// packed f32x2 FMAs (weight LDS.128 broadcast amortized over 2 rows, h read
// as float4 per 4 kk). Partial sums combined via smem + add.rn.f32x2; each
// thread then owns batch row `tid` for the fused LSTM-cell epilogue.
// ---------------------------------------------------------------------------
__global__ __launch_bounds__(256, 1) void lstm_persist_kernel(
    const float* __restrict__ G,      // S*B x 4H (biases included)
    float* __restrict__ hb,           // 2*B*H double buffer (init in buf 0)
    float* __restrict__ c_st,         // B*H
    const float* __restrict__ done,   // S*B
    const float* __restrict__ Whh,    // 4H x H
    float* __restrict__ raw_out)      // S*B*H unmasked h stream
{
    extern __shared__ float sm[];
    float* Ws = sm;                         // [512][16] k-major, 64B rows
    float* Hs = sm + 8192;                  // 4 buffers of [256][36]
    u64*   Xs = (u64*)(sm + 8192 + 4 * HBUF_);  // 256 threads x 8 u64 exchange

    const int tid = threadIdx.x;
    const int nt0 = blockIdx.x * 4;

    // ---- load weight slice once: Ws[k][g*4+c] = Whh[g*H + nt0+c][k] ----
    {
        const int p = tid & 15, g = p >> 2, c = p & 3;
        const float* wrow = Whh + (size_t)(g * H_ + nt0 + c) * H_;
        const int kq = tid >> 4;          // 0..15
#pragma unroll
        for (int it = 0; it < 8; it++) {
            int k4 = (kq + it * 16) * 4;
            float4 v = *(const float4*)(wrow + k4);
            Ws[(k4 + 0) * 16 + p] = v.x;
            Ws[(k4 + 1) * 16 + p] = v.y;
            Ws[(k4 + 2) * 16 + p] = v.z;
            Ws[(k4 + 3) * 16 + p] = v.w;
        }
    }
    __syncthreads();

    const int khalf = tid >> 7;           // 0: k[0,256)  1: k[256,512)
    const int u     = tid & 127;
    const int j8    = u & 7;              // k-quad within chunk (32 floats)
    const int brow  = u >> 3;             // 0..15 staging row base
    const int kbase = khalf * 256;
    float* HsG = Hs + khalf * 2 * HBUF_;  // this group's double buffer
    const int r0 = u;                     // rows r0 and r0+128

    for (int t = 0; t < S_; t++) {
        const float* h_in = hb + (t & 1) * BH_;
        float* h_out      = hb + ((t + 1) & 1) * BH_;

        // ---- prefetch epilogue operands for row `tid` (hidden by k-loop) ----
        const float mEp = 1.0f - __ldg(done + t * B_ + tid);
        const float* Gt = G + ((size_t)t * B_ + tid) * G4_ + nt0;
        float4 gI = __ldg((const float4*)(Gt));
        float4 gF = __ldg((const float4*)(Gt + H_));
        float4 gGv = __ldg((const float4*)(Gt + 2 * H_));
        float4 gO = __ldg((const float4*)(Gt + 3 * H_));
        float4 cp = __ldcg((const float4*)(c_st + (size_t)tid * H_ + nt0));

        u64 acc[16];
#pragma unroll
        for (int p = 0; p < 16; p++) acc[p] = 0ull;

        // ---- stage chunk 0 of this group's k-half ----
        float4 rb[16];
#pragma unroll
        for (int it = 0; it < 16; it++)
            rb[it] = __ldcg((const float4*)(h_in + (size_t)(it * 16 + brow) * H_ + kbase + j8 * 4));
        {
            float* hd = HsG;
#pragma unroll
            for (int it = 0; it < 16; it++) {
                float* d = hd + (it * 16 + brow) * HSTR_ + j8 * 4;
                d[0] = rb[it].x; d[1] = rb[it].y; d[2] = rb[it].z; d[3] = rb[it].w;
            }
        }
        __syncthreads();

        // ---- 8 chunks of 32 kk, single sync per chunk ----
#pragma unroll 1
        for (int c = 0; c < 8; c++) {
            const bool more = (c + 1 < 8);
            if (more) {
#pragma unroll
                for (int it = 0; it < 16; it++)
                    rb[it] = __ldcg((const float4*)(h_in + (size_t)(it * 16 + brow) * H_ +
                                                    kbase + (c + 1) * KC_ + j8 * 4));
            }
            const float* h0p = HsG + (c & 1) * HBUF_ + r0 * HSTR_;
            const float* h1p = h0p + 128 * HSTR_;
            const float* wsk = Ws + (kbase + c * KC_) * 16;
#pragma unroll
            for (int q = 0; q < 8; q++) {           // 4 kk per group
                float4 ha = *(const float4*)(h0p + q * 4);
                float4 hbv = *(const float4*)(h1p + q * 4);
                float hav[4] = {ha.x, ha.y, ha.z, ha.w};
                float hbvv[4] = {hbv.x, hbv.y, hbv.z, hbv.w};
#pragma unroll
                for (int j = 0; j < 4; j++) {
                    u64 aa = pack2(hav[j], hav[j]);
                    u64 bb = pack2(hbvv[j], hbvv[j]);
                    const ulonglong2* wp = (const ulonglong2*)(wsk + (q * 4 + j) * 16);
                    ulonglong2 w0 = wp[0], w1 = wp[1], w2 = wp[2], w3 = wp[3];
                    acc[0] = fma2(aa, w0.x, acc[0]);
                    acc[1] = fma2(aa, w0.y, acc[1]);
                    acc[2] = fma2(aa, w1.x, acc[2]);
                    acc[3] = fma2(aa, w1.y, acc[3]);
                    acc[4] = fma2(aa, w2.x, acc[4]);
                    acc[5] = fma2(aa, w2.y, acc[5]);
                    acc[6] = fma2(aa, w3.x, acc[6]);
                    acc[7] = fma2(aa, w3.y, acc[7]);
                    acc[8]  = fma2(bb, w0.x, acc[8]);
                    acc[9]  = fma2(bb, w0.y, acc[9]);
                    acc[10] = fma2(bb, w1.x, acc[10]);
                    acc[11] = fma2(bb, w1.y, acc[11]);
                    acc[12] = fma2(bb, w2.x, acc[12]);
                    acc[13] = fma2(bb, w2.y, acc[13]);
                    acc[14] = fma2(bb, w3.x, acc[14]);
                    acc[15] = fma2(bb, w3.y, acc[15]);
                }
            }
            if (more) {
                float* hd = HsG + ((c + 1) & 1) * HBUF_;
#pragma unroll
                for (int it = 0; it < 16; it++) {
                    float* d = hd + (it * 16 + brow) * HSTR_ + j8 * 4;
                    d[0] = rb[it].x; d[1] = rb[it].y; d[2] = rb[it].z; d[3] = rb[it].w;
                }
            }
            __syncthreads();
        }

        // ---- combine k-halves: each thread ends owning row `tid` ----
        // acc[0..7] = row r0, acc[8..15] = row r0+128.
        // khalf 0 (tid<128): own row tid=r0, publish acc[8..15].
        // khalf 1 (tid>=128): own row tid=r0+128, publish acc[0..7].
        {
            const int pub = khalf ? 0 : 8;
#pragma unroll
            for (int j = 0; j < 8; j++) Xs[tid * 8 + j] = acc[pub + j];
            __syncthreads();
            const u64* part = Xs + (tid ^ 128) * 8;
            const int own = khalf ? 8 : 0;
#pragma unroll
            for (int j = 0; j < 8; j++) acc[j] = add2(acc[own + j], part[j]);
        }

        // ---- epilogue: LSTM cell for batch row b = tid, cols nt0..nt0+3 ----
        {
            const int b = tid;
            float2 a0 = unpack2(acc[0]), a1 = unpack2(acc[1]);
            float2 a2 = unpack2(acc[2]), a3 = unpack2(acc[3]);
            float2 a4 = unpack2(acc[4]), a5 = unpack2(acc[5]);
            float2 a6 = unpack2(acc[6]), a7 = unpack2(acc[7]);

            float vi[4] = {a0.x + gI.x,  a0.y + gI.y,  a1.x + gI.z,  a1.y + gI.w};
            float vf[4] = {a2.x + gF.x,  a2.y + gF.y,  a3.x + gF.z,  a3.y + gF.w};
            float vg[4] = {a4.x + gGv.x, a4.y + gGv.y, a5.x + gGv.z, a5.y + gGv.w};
            float vo[4] = {a6.x + gO.x,  a6.y + gO.y,  a7.x + gO.z,  a7.y + gO.w};
            float vc[4] = {cp.x, cp.y, cp.z, cp.w};

            float hn[4], cn[4];
#pragma unroll
            for (int c2 = 0; c2 < 4; c2++) {
                float si = fsig(vi[c2]);
                float sf = fsig(vf[c2]);
                float so = fsig(vo[c2]);
                float cnew = sf * vc[c2] + si * ftanh(vg[c2]);
                hn[c2] = so * ftanh(cnew);
                cn[c2] = cnew;
            }

            float4 rawv = {hn[0], hn[1], hn[2], hn[3]};
            *(float4*)(raw_out + (size_t)t * BH_ + (size_t)b * H_ + nt0) = rawv;
            float4 hv4 = {hn[0] * mEp, hn[1] * mEp, hn[2] * mEp, hn[3] * mEp};
            *(float4*)(h_out + (size_t)b * H_ + nt0) = hv4;
            float4 cv4 = {cn[0] * mEp, cn[1] * mEp, cn[2] * mEp, cn[3] * mEp};
            *(float4*)(c_st + (size_t)b * H_ + nt0) = cv4;
        }

        // ---- grid barrier (release: fence+arrive; acquire: spin) ----
        if (t + 1 < S_) {
            __threadfence();
            __syncthreads();
            if (tid == 0) {
                atomicAdd(&g_sync, 1u);
                unsigned target = (unsigned)NCTA_ * (unsigned)(t + 1);
                while (*((volatile unsigned*)&g_sync) < target) { }
            }
            __syncthreads();
        }
    }
}

// ---------------------------------------------------------------------------
__global__ void copy2_kernel(const float* __restrict__ a, const float* __restrict__ b,
                             float* __restrict__ oa, float* __restrict__ ob, int n)
{
    int i = blockIdx.x * blockDim.x + threadIdx.x;
    if (i < n) { oa[i] = a[i]; ob[i] = b[i]; }
}

// ---------------------------------------------------------------------------
extern "C" void kernel_launch(void* const* d_in, const int* in_sizes, int n_in,
                              void* d_out, int out_size)
{
    const float* x    = (const float*)d_in[0];
    const float* h0   = (const float*)d_in[1];
    const float* c0   = (const float*)d_in[2];
    const float* done = (const float*)d_in[3];
    const float* Wih0 = (const float*)d_in[4];
    const float* Whh0 = (const float*)d_in[5];
    const float* bih0 = (const float*)d_in[6];
    const float* bhh0 = (const float*)d_in[7];
    const float* Wih1 = (const float*)d_in[8];
    const float* Whh1 = (const float*)d_in[9];
    const float* bih1 = (const float*)d_in[10];
    const float* bhh1 = (const float*)d_in[11];
    float* out = (float*)d_out;

    float *G, *H0raw, *hb, *cb;
    cudaGetSymbolAddress((void**)&G, g_G);
    cudaGetSymbolAddress((void**)&H0raw, g_H0raw);
    cudaGetSymbolAddress((void**)&hb, g_hbuf);
    cudaGetSymbolAddress((void**)&cb, g_cbuf);

    // No static guard (harness rule); idempotent + capture-safe (non-stream API).
    cudaFuncSetAttribute(lstm_persist_kernel,
                         cudaFuncAttributeMaxDynamicSharedMemorySize, SMEM_BYTES_);

    const bool write_states =
        out_size >= (int)((size_t)S_ * BH_ + 2 * (size_t)L_ * BH_);
    float* out_h = out + (size_t)S_ * BH_;
    float* out_c = out + (size_t)S_ * BH_ + (size_t)L_ * BH_;

    const dim3 ggrid(G4_ / 128, (S_ * B_) / 128);
    const int cblk = (BH_ + 255) / 256;

    // ===================== Layer 0 =====================
    copy2_kernel<<<cblk, 256>>>(h0, c0, hb, cb, BH_);
    gemm_bias_kernel<<<ggrid, 256>>>(x, Wih0, bih0, bhh0, G, S_ * B_, G4_, I_);
    reset_sync_kernel<<<1, 1>>>();
    lstm_persist_kernel<<<NCTA_, 256, SMEM_BYTES_>>>(G, hb, cb, done, Whh0, H0raw);
    if (write_states)
        copy2_kernel<<<cblk, 256>>>(hb, cb, out_h, out_c, BH_);

    // ===================== Layer 1 =====================
    copy2_kernel<<<cblk, 256>>>(h0 + BH_, c0 + BH_, hb, cb, BH_);
    gemm_bias_kernel<<<ggrid, 256>>>(H0raw, Wih1, bih1, bhh1, G, S_ * B_, G4_, H_);
    reset_sync_kernel<<<1, 1>>>();
    lstm_persist_kernel<<<NCTA_, 256, SMEM_BYTES_>>>(G, hb, cb, done, Whh1, out);
    if (write_states)
        copy2_kernel<<<cblk, 256>>>(hb, cb, out_h + BH_, out_c + BH_, BH_);
}